// round 15
// baseline (speedup 1.0000x reference)
#include <cuda_runtime.h>
#include <cuda_fp16.h>

#define N1C 8192
#define N2C 8192
#define BC  2
#define NSPLIT 2              // point-dimension splits (grid.y)
#define SPAN (N1C / NSPLIT)   // 4096 points per block
#define TILE 2048
#define WPB 8                 // warps per block (all share one query set)
#define SLICE (TILE / WPB)    // 256 points = 128 pairs per warp per tile
#define QPB 32                // queries per block = one per lane
#define NSAMP 64              // pre-pass samples per query
#define PAIRS (TILE / 2)      // 1024 pairs per tile
#define NQ (BC * N2C)

__device__ float g_tau[NQ];               // per-query 3rd-best fast-form bound
__device__ float g_d2[NSPLIT * 3][NQ];    // transposed scratch: coalesced merge
__device__ int   g_i2[NSPLIT * 3][NQ];

__device__ __forceinline__ bool kvless(float ad, int ai, float bd, int bi) {
    return ad < bd || (ad == bd && ai < bi);
}

// reference-rounding sum of squares: fl(fl(x*x + y*y) + z*z), squares rounded
__device__ __forceinline__ float sqsum_ref(float x, float y, float z) {
    float xx = __fmul_rn(x, x);
    float yy = __fmul_rn(y, y);
    float zz = __fmul_rn(z, z);
    return __fadd_rn(__fadd_rn(xx, yy), zz);
}

// warm-up: per query, 3rd-smallest fast distance over 64 strided samples.
__global__ __launch_bounds__(256) void knn_pretau(
    const float* __restrict__ p1, const float* __restrict__ p2)
{
    int gq = blockIdx.x * blockDim.x + threadIdx.x;
    int b = gq >> 13;
    int m = gq & (N2C - 1);
    const float* q = p2 + ((size_t)b * N2C + m) * 3;
    float qx = q[0], qy = q[1], qz = q[2];
    float nx = -2.0f * qx, ny = -2.0f * qy, nz = -2.0f * qz;
    const float* pb = p1 + (size_t)b * N1C * 3;

    float v0 = 3.4e38f, v1 = 3.4e38f, v2 = 3.4e38f;
    #pragma unroll 8
    for (int k = 0; k < NSAMP; k++) {
        const float* p = pb + (size_t)(k * (N1C / NSAMP)) * 3;  // warp-uniform
        float x = p[0], y = p[1], z = p[2];
        float w = sqsum_ref(x, y, z);
        float df = fmaf(nz, z, fmaf(ny, y, fmaf(nx, x, w)));
        float lo0 = fminf(df, v0);  float hi0 = fmaxf(df, v0);  v0 = lo0;
        float lo1 = fminf(hi0, v1); float hi1 = fmaxf(hi0, v1); v1 = lo1;
        v2 = fminf(hi1, v2);
    }
    g_tau[gq] = v2;   // fast-form domain (excludes sq2)
}

__global__ __launch_bounds__(256) void knn_main(
    const float* __restrict__ p1, const float* __restrict__ p2)
{
    __shared__ uint4  ht[PAIRS];         // per pair: {x2,y2,z2,w2} half2-packed
    __shared__ float  md[QPB][WPB][3];   // per-warp partial top-3 dists
    __shared__ int    mi[QPB][WPB][3];   // per-warp partial top-3 idxs
    __shared__ float  tau_s[QPB];        // cross-warp shared 3rd-best bound

    const int b     = blockIdx.z;
    const int split = blockIdx.y;
    const int lane  = threadIdx.x & 31;
    const int warp  = threadIdx.x >> 5;
    const int m     = blockIdx.x * QPB + lane;   // query id of this lane
    const int gq    = (b << 13) + m;

    volatile float* tau_v = tau_s;

    const float* q = p2 + (size_t)gq * 3;
    const float qx = q[0], qy = q[1], qz = q[2];
    const float nx = -2.0f * qx, ny = -2.0f * qy, nz = -2.0f * qz; // exact
    const float sq2 = sqsum_ref(qx, qy, qz);
    // fp16 filter error band (worst-case chain err + fast-path diff + ties)
    const float band = 0.025f + 0.008f * sq2;

    const __half2 nx2 = __float2half2_rn(nx);
    const __half2 ny2 = __float2half2_rn(ny);
    const __half2 nz2 = __float2half2_rn(nz);

    float b0 = 3.4e38f, b1 = 3.4e38f, b2 = 3.4e38f;
    int   i0 = 0, i1 = 0, i2 = 0;

    // seed shared tau from the pre-pass (exact domain = fast + sq2)
    if (warp == 0) tau_s[lane] = g_tau[gq] + sq2;

    const float* pb = p1 + (size_t)b * N1C * 3;
    const int base = split * SPAN;

    for (int t0 = base; t0 < base + SPAN; t0 += TILE) {
        __syncthreads();
        // cooperative tile build: pack pairs of points into half2 quads
        for (int i = threadIdx.x; i < PAIRS; i += blockDim.x) {
            const float* p = pb + (size_t)(t0 + 2 * i) * 3;
            float x0 = p[0], y0 = p[1], z0 = p[2];
            float x1 = p[3], y1 = p[4], z1 = p[5];
            float w0 = sqsum_ref(x0, y0, z0);
            float w1 = sqsum_ref(x1, y1, z1);
            __half2 X = __floats2half2_rn(x0, x1);
            __half2 Y = __floats2half2_rn(y0, y1);
            __half2 Z = __floats2half2_rn(z0, z1);
            __half2 W = __floats2half2_rn(w0, w1);
            uint4 v;
            v.x = *(unsigned*)&X; v.y = *(unsigned*)&Y;
            v.z = *(unsigned*)&Z; v.w = *(unsigned*)&W;
            ht[i] = v;
        }
        __syncthreads();

        // this warp scans its 128-pair slice; ALL lanes read the SAME pair
        // (broadcast LDS.128) and test it against their own query.
        const uint4* hp = ht + warp * (SLICE / 2);
        const int jb = t0 + warp * SLICE;

        for (int c = 0; c < SLICE / 64; ++c) {      // 32 pairs per chunk
            // refresh shared threshold (races benign; stale tau only ADDS
            // candidate bits, never drops one)
            float t = fminf(tau_v[lane], b2);
            tau_v[lane] = t;
            const float tauf = __fadd_rn(t, -sq2) + band;
            const __half2 tau2 = __half2half2(__float2half_ru(tauf));
            const unsigned tauu = *(const unsigned*)&tau2;

            const uint4* cp = hp + c * 32;

            // ---- phase 1: 32 pairs, branch-free candidate mask
            unsigned mska = 0u, mskb = 0u;

#define KNN_STEP(K, MSK)                                                     \
            {                                                                \
                uint4 v = cp[K];                                             \
                __half2 X = *(__half2*)&v.x, Y = *(__half2*)&v.y;            \
                __half2 Z = *(__half2*)&v.z, W = *(__half2*)&v.w;            \
                __half2 df2 = __hfma2(nz2, Z,                                \
                               __hfma2(ny2, Y, __hfma2(nx2, X, W)));         \
                unsigned dfu = *(unsigned*)&df2;                             \
                asm("{ .reg .pred p, q;\n\t"                                 \
                    "setp.lt.f16x2 p|q, %1, %2;\n\t"                         \
                    "@p or.b32 %0, %0, %3;\n\t"                              \
                    "@q or.b32 %0, %0, %3; }"                                \
                    : "+r"(MSK) : "r"(dfu), "r"(tauu), "n"(1u << (K)));      \
            }

            KNN_STEP(0,  mska) KNN_STEP(1,  mskb) KNN_STEP(2,  mska) KNN_STEP(3,  mskb)
            KNN_STEP(4,  mska) KNN_STEP(5,  mskb) KNN_STEP(6,  mska) KNN_STEP(7,  mskb)
            KNN_STEP(8,  mska) KNN_STEP(9,  mskb) KNN_STEP(10, mska) KNN_STEP(11, mskb)
            KNN_STEP(12, mska) KNN_STEP(13, mskb) KNN_STEP(14, mska) KNN_STEP(15, mskb)
            KNN_STEP(16, mska) KNN_STEP(17, mskb) KNN_STEP(18, mska) KNN_STEP(19, mskb)
            KNN_STEP(20, mska) KNN_STEP(21, mskb) KNN_STEP(22, mska) KNN_STEP(23, mskb)
            KNN_STEP(24, mska) KNN_STEP(25, mskb) KNN_STEP(26, mska) KNN_STEP(27, mskb)
            KNN_STEP(28, mska) KNN_STEP(29, mskb) KNN_STEP(30, mska) KNN_STEP(31, mskb)
#undef KNN_STEP

            unsigned mask = mska | mskb;

            // ---- phase 2: rare exact re-check (both points of flagged
            // pair, ascending order) + lex insert
            while (mask) {
                int k = __ffs(mask) - 1;
                mask &= mask - 1;
                int j0 = jb + (c * 32 + k) * 2;
                #pragma unroll
                for (int t2 = 0; t2 < 2; ++t2) {
                    int j = j0 + t2;
                    const float* p = pb + (size_t)j * 3;
                    float x = p[0], y = p[1], z = p[2];
                    float w = sqsum_ref(x, y, z);
                    // exact reference-rounded distance
                    float m0 = __fmul_rn(qx, x);
                    float m1 = __fmul_rn(qy, y);
                    float m2 = __fmul_rn(qz, z);
                    float inner = __fadd_rn(__fadd_rn(m0, m1), m2);
                    float ssum  = __fadd_rn(sq2, w);
                    float d     = fmaf(-2.0f, inner, ssum);
                    if (d < b2) {
                        if (d < b1) {
                            b2 = b1; i2 = i1;
                            if (d < b0) { b1 = b0; i1 = i0; b0 = d; i0 = j; }
                            else        { b1 = d;  i1 = j; }
                        } else { b2 = d; i2 = j; }
                    }
                }
            }
        }
    }

    // publish this warp's partial triple for its 32 queries
    md[lane][warp][0] = b0; md[lane][warp][1] = b1; md[lane][warp][2] = b2;
    mi[lane][warp][0] = i0; mi[lane][warp][1] = i1; mi[lane][warp][2] = i2;
    __syncthreads();

    // warp 0 merges the 8 partial triples per query (lane = query), then
    // writes ONE triple to the transposed scratch (coalesced across lanes).
    if (warp == 0) {
        float B0 = 3.4e38f, B1 = 3.4e38f, B2 = 3.4e38f;
        int   I0 = 0x7fffffff, I1 = 0x7fffffff, I2 = 0x7fffffff;
        #pragma unroll
        for (int w = 0; w < WPB; ++w) {
            #pragma unroll
            for (int r = 0; r < 3; ++r) {
                float d = md[lane][w][r];
                int   j = mi[lane][w][r];
                if (kvless(d, j, B2, I2)) {
                    if (kvless(d, j, B1, I1)) {
                        B2 = B1; I2 = I1;
                        if (kvless(d, j, B0, I0)) { B1 = B0; I1 = I0; B0 = d; I0 = j; }
                        else                      { B1 = d;  I1 = j; }
                    } else { B2 = d; I2 = j; }
                }
            }
        }
        g_d2[split * 3 + 0][gq] = B0; g_i2[split * 3 + 0][gq] = I0;
        g_d2[split * 3 + 1][gq] = B1; g_i2[split * 3 + 1][gq] = I1;
        g_d2[split * 3 + 2][gq] = B2; g_i2[split * 3 + 2][gq] = I2;
    }
}

__global__ __launch_bounds__(256) void knn_merge(
    const float* __restrict__ c1, float* __restrict__ out)
{
    int gq = blockIdx.x * blockDim.x + threadIdx.x;   // 0 .. NQ-1
    if (gq >= NQ) return;
    int b = gq >> 13;
    // lex top-3 of distinct (d, idx) pairs is order-independent
    float B0 = 3.4e38f, B1 = 3.4e38f, B2 = 3.4e38f;
    int   I0 = 0x7fffffff, I1 = 0x7fffffff, I2 = 0x7fffffff;
    #pragma unroll
    for (int t = 0; t < NSPLIT * 3; ++t) {
        float d = g_d2[t][gq];      // coalesced across threads
        int   j = g_i2[t][gq];
        if (kvless(d, j, B2, I2)) {
            if (kvless(d, j, B1, I1)) {
                B2 = B1; I2 = I1;
                if (kvless(d, j, B0, I0)) { B1 = B0; I1 = I0; B0 = d; I0 = j; }
                else                      { B1 = d;  I1 = j; }
            } else { B2 = d; I2 = j; }
        }
    }

    const float* cb = c1 + (size_t)b * N1C * 3;
    const float* ca = cb + (size_t)I0 * 3;   // rank-0 neighbor
    const float* cc = cb + (size_t)I1 * 3;   // rank-1
    const float* cd = cb + (size_t)I2 * 3;   // rank-2
    float* o = out + (size_t)gq * 3;
    #pragma unroll
    for (int c = 0; c < 3; c++) {
        // jnp.mean over K: rn(rn(rn(c0+c1)+c2) / 3)
        float ssum = __fadd_rn(__fadd_rn(ca[c], cc[c]), cd[c]);
        o[c] = __fdiv_rn(ssum, 3.0f);
    }
}

extern "C" void kernel_launch(void* const* d_in, const int* in_sizes, int n_in,
                              void* d_out, int out_size) {
    const float* p1 = (const float*)d_in[0];   // points1 [B, N1, 3]
    const float* p2 = (const float*)d_in[1];   // points2 [B, N2, 3]
    const float* c1 = (const float*)d_in[2];   // colors1 [B, N1, 3]
    float* out = (float*)d_out;                // [B, N2, 3] f32

    knn_pretau<<<(NQ + 255) / 256, 256>>>(p1, p2);
    dim3 grid(N2C / QPB, NSPLIT, BC);
    knn_main<<<grid, 256>>>(p1, p2);
    knn_merge<<<(NQ + 255) / 256, 256>>>(c1, out);
}

// round 16
// speedup vs baseline: 1.0265x; 1.0265x over previous
#include <cuda_runtime.h>
#include <cuda_fp16.h>

#define N1C 8192
#define N2C 8192
#define BC  2
#define NSPLIT 2              // point-dimension splits (grid.y)
#define SPAN (N1C / NSPLIT)   // 4096 points per block
#define TILE 2048
#define WPB 8                 // warps per block (all share one query set)
#define SLICE (TILE / WPB)    // 256 points = 128 pairs per warp per tile
#define QPB 32                // queries per block = one per lane
#define NSAMP 64              // pre-pass samples per query
#define PAIRS (TILE / 2)      // 1024 pairs per tile
#define NQ (BC * N2C)

__device__ float g_tau[NQ];               // per-query 3rd-best fast-form bound
__device__ float g_d2[NSPLIT * 3][NQ];    // transposed scratch: coalesced merge
__device__ int   g_i2[NSPLIT * 3][NQ];

__device__ __forceinline__ bool kvless(float ad, int ai, float bd, int bi) {
    return ad < bd || (ad == bd && ai < bi);
}

// reference-rounding sum of squares: fl(fl(x*x + y*y) + z*z), squares rounded
__device__ __forceinline__ float sqsum_ref(float x, float y, float z) {
    float xx = __fmul_rn(x, x);
    float yy = __fmul_rn(y, y);
    float zz = __fmul_rn(z, z);
    return __fadd_rn(__fadd_rn(xx, yy), zz);
}

// warm-up: per query, 3rd-smallest fast distance over 64 strided samples.
// 8 lanes per query: each lane samples 8 points, then a 3-stage shfl
// truncated odd-even merge yields the exact 3rd-smallest of the union.
__global__ __launch_bounds__(256) void knn_pretau(
    const float* __restrict__ p1, const float* __restrict__ p2)
{
    const int l  = threadIdx.x & 7;               // lane within query group
    const int g  = threadIdx.x >> 3;              // query group in block (0..31)
    const int gq = blockIdx.x * 32 + g;           // global query id
    const int b  = gq >> 13;
    const int m  = gq & (N2C - 1);

    const float* q = p2 + ((size_t)b * N2C + m) * 3;
    float qx = q[0], qy = q[1], qz = q[2];
    float nx = -2.0f * qx, ny = -2.0f * qy, nz = -2.0f * qz;
    const float* pb = p1 + (size_t)b * N1C * 3;

    float v0 = 3.4e38f, v1 = 3.4e38f, v2 = 3.4e38f;
    #pragma unroll
    for (int t = 0; t < NSAMP / 8; t++) {
        int idx = (l * (NSAMP / 8) + t) * (N1C / NSAMP);
        const float* p = pb + (size_t)idx * 3;
        float x = p[0], y = p[1], z = p[2];
        float w = sqsum_ref(x, y, z);
        float df = fmaf(nz, z, fmaf(ny, y, fmaf(nx, x, w)));
        // branch-free 3-smallest (values only)
        float lo0 = fminf(df, v0);  float hi0 = fmaxf(df, v0);  v0 = lo0;
        float lo1 = fminf(hi0, v1); float hi1 = fmaxf(hi0, v1); v1 = lo1;
        v2 = fminf(hi1, v2);
    }
    // values-only truncated odd-even merge across the 8 lanes (xor 1,2,4)
    #pragma unroll
    for (int off = 1; off < 8; off <<= 1) {
        float o0 = __shfl_xor_sync(0xffffffffu, v0, off);
        float o1 = __shfl_xor_sync(0xffffffffu, v1, off);
        float o2 = __shfl_xor_sync(0xffffffffu, v2, off);
        float M0 = fmaxf(v0, o0);
        float m1 = fminf(v1, o1);
        float m2 = fminf(v2, o2);
        v0 = fminf(v0, o0);
        v1 = fminf(M0, m1);
        v2 = fminf(fmaxf(M0, m1), m2);
    }
    if (l == 0) g_tau[gq] = v2;   // fast-form domain (excludes sq2)
}

__global__ __launch_bounds__(256) void knn_main(
    const float* __restrict__ p1, const float* __restrict__ p2)
{
    __shared__ uint4  ht[PAIRS];         // per pair: {x2,y2,z2,w2} half2-packed
    __shared__ float  md[QPB][WPB][3];   // per-warp partial top-3 dists
    __shared__ int    mi[QPB][WPB][3];   // per-warp partial top-3 idxs
    __shared__ float  tau_s[QPB];        // cross-warp shared 3rd-best bound

    const int b     = blockIdx.z;
    const int split = blockIdx.y;
    const int lane  = threadIdx.x & 31;
    const int warp  = threadIdx.x >> 5;
    const int m     = blockIdx.x * QPB + lane;   // query id of this lane
    const int gq    = (b << 13) + m;

    volatile float* tau_v = tau_s;

    const float* q = p2 + (size_t)gq * 3;
    const float qx = q[0], qy = q[1], qz = q[2];
    const float nx = -2.0f * qx, ny = -2.0f * qy, nz = -2.0f * qz; // exact
    const float sq2 = sqsum_ref(qx, qy, qz);
    // fp16 filter error band (worst-case chain err + fast-path diff + ties)
    const float band = 0.025f + 0.008f * sq2;

    const __half2 nx2 = __float2half2_rn(nx);
    const __half2 ny2 = __float2half2_rn(ny);
    const __half2 nz2 = __float2half2_rn(nz);

    float b0 = 3.4e38f, b1 = 3.4e38f, b2 = 3.4e38f;
    int   i0 = 0, i1 = 0, i2 = 0;

    // seed shared tau from the pre-pass (exact domain = fast + sq2)
    if (warp == 0) tau_s[lane] = g_tau[gq] + sq2;

    const float* pb = p1 + (size_t)b * N1C * 3;
    const int base = split * SPAN;

    for (int t0 = base; t0 < base + SPAN; t0 += TILE) {
        __syncthreads();
        // cooperative tile build: pack pairs of points into half2 quads
        for (int i = threadIdx.x; i < PAIRS; i += blockDim.x) {
            const float* p = pb + (size_t)(t0 + 2 * i) * 3;
            float x0 = p[0], y0 = p[1], z0 = p[2];
            float x1 = p[3], y1 = p[4], z1 = p[5];
            float w0 = sqsum_ref(x0, y0, z0);
            float w1 = sqsum_ref(x1, y1, z1);
            __half2 X = __floats2half2_rn(x0, x1);
            __half2 Y = __floats2half2_rn(y0, y1);
            __half2 Z = __floats2half2_rn(z0, z1);
            __half2 W = __floats2half2_rn(w0, w1);
            uint4 v;
            v.x = *(unsigned*)&X; v.y = *(unsigned*)&Y;
            v.z = *(unsigned*)&Z; v.w = *(unsigned*)&W;
            ht[i] = v;
        }
        __syncthreads();

        // this warp scans its 128-pair slice; ALL lanes read the SAME pair
        // (broadcast LDS.128) and test it against their own query.
        const uint4* hp = ht + warp * (SLICE / 2);
        const int jb = t0 + warp * SLICE;

        for (int c = 0; c < SLICE / 64; ++c) {      // 32 pairs per chunk
            // refresh shared threshold (races benign; stale tau only ADDS
            // candidate bits, never drops one)
            float t = fminf(tau_v[lane], b2);
            tau_v[lane] = t;
            const float tauf = __fadd_rn(t, -sq2) + band;
            const __half2 tau2 = __half2half2(__float2half_ru(tauf));
            const unsigned tauu = *(const unsigned*)&tau2;

            const uint4* cp = hp + c * 32;

            // ---- phase 1: 32 pairs, branch-free candidate mask
            unsigned mska = 0u, mskb = 0u;

#define KNN_STEP(K, MSK)                                                     \
            {                                                                \
                uint4 v = cp[K];                                             \
                __half2 X = *(__half2*)&v.x, Y = *(__half2*)&v.y;            \
                __half2 Z = *(__half2*)&v.z, W = *(__half2*)&v.w;            \
                __half2 df2 = __hfma2(nz2, Z,                                \
                               __hfma2(ny2, Y, __hfma2(nx2, X, W)));         \
                unsigned dfu = *(unsigned*)&df2;                             \
                asm("{ .reg .pred p, q;\n\t"                                 \
                    "setp.lt.f16x2 p|q, %1, %2;\n\t"                         \
                    "@p or.b32 %0, %0, %3;\n\t"                              \
                    "@q or.b32 %0, %0, %3; }"                                \
                    : "+r"(MSK) : "r"(dfu), "r"(tauu), "n"(1u << (K)));      \
            }

            KNN_STEP(0,  mska) KNN_STEP(1,  mskb) KNN_STEP(2,  mska) KNN_STEP(3,  mskb)
            KNN_STEP(4,  mska) KNN_STEP(5,  mskb) KNN_STEP(6,  mska) KNN_STEP(7,  mskb)
            KNN_STEP(8,  mska) KNN_STEP(9,  mskb) KNN_STEP(10, mska) KNN_STEP(11, mskb)
            KNN_STEP(12, mska) KNN_STEP(13, mskb) KNN_STEP(14, mska) KNN_STEP(15, mskb)
            KNN_STEP(16, mska) KNN_STEP(17, mskb) KNN_STEP(18, mska) KNN_STEP(19, mskb)
            KNN_STEP(20, mska) KNN_STEP(21, mskb) KNN_STEP(22, mska) KNN_STEP(23, mskb)
            KNN_STEP(24, mska) KNN_STEP(25, mskb) KNN_STEP(26, mska) KNN_STEP(27, mskb)
            KNN_STEP(28, mska) KNN_STEP(29, mskb) KNN_STEP(30, mska) KNN_STEP(31, mskb)
#undef KNN_STEP

            unsigned mask = mska | mskb;

            // ---- phase 2: rare exact re-check (both points of flagged
            // pair, ascending order) + lex insert
            while (mask) {
                int k = __ffs(mask) - 1;
                mask &= mask - 1;
                int j0 = jb + (c * 32 + k) * 2;
                #pragma unroll
                for (int t2 = 0; t2 < 2; ++t2) {
                    int j = j0 + t2;
                    const float* p = pb + (size_t)j * 3;
                    float x = p[0], y = p[1], z = p[2];
                    float w = sqsum_ref(x, y, z);
                    // exact reference-rounded distance
                    float m0 = __fmul_rn(qx, x);
                    float m1 = __fmul_rn(qy, y);
                    float m2 = __fmul_rn(qz, z);
                    float inner = __fadd_rn(__fadd_rn(m0, m1), m2);
                    float ssum  = __fadd_rn(sq2, w);
                    float d     = fmaf(-2.0f, inner, ssum);
                    if (d < b2) {
                        if (d < b1) {
                            b2 = b1; i2 = i1;
                            if (d < b0) { b1 = b0; i1 = i0; b0 = d; i0 = j; }
                            else        { b1 = d;  i1 = j; }
                        } else { b2 = d; i2 = j; }
                    }
                }
            }
        }
    }

    // publish this warp's partial triple for its 32 queries
    md[lane][warp][0] = b0; md[lane][warp][1] = b1; md[lane][warp][2] = b2;
    mi[lane][warp][0] = i0; mi[lane][warp][1] = i1; mi[lane][warp][2] = i2;
    __syncthreads();

    // warp 0 merges the 8 partial triples per query (lane = query), then
    // writes ONE triple to the transposed scratch (coalesced across lanes).
    if (warp == 0) {
        float B0 = 3.4e38f, B1 = 3.4e38f, B2 = 3.4e38f;
        int   I0 = 0x7fffffff, I1 = 0x7fffffff, I2 = 0x7fffffff;
        #pragma unroll
        for (int w = 0; w < WPB; ++w) {
            #pragma unroll
            for (int r = 0; r < 3; ++r) {
                float d = md[lane][w][r];
                int   j = mi[lane][w][r];
                if (kvless(d, j, B2, I2)) {
                    if (kvless(d, j, B1, I1)) {
                        B2 = B1; I2 = I1;
                        if (kvless(d, j, B0, I0)) { B1 = B0; I1 = I0; B0 = d; I0 = j; }
                        else                      { B1 = d;  I1 = j; }
                    } else { B2 = d; I2 = j; }
                }
            }
        }
        g_d2[split * 3 + 0][gq] = B0; g_i2[split * 3 + 0][gq] = I0;
        g_d2[split * 3 + 1][gq] = B1; g_i2[split * 3 + 1][gq] = I1;
        g_d2[split * 3 + 2][gq] = B2; g_i2[split * 3 + 2][gq] = I2;
    }
}

__global__ __launch_bounds__(256) void knn_merge(
    const float* __restrict__ c1, float* __restrict__ out)
{
    int gq = blockIdx.x * blockDim.x + threadIdx.x;   // 0 .. NQ-1
    if (gq >= NQ) return;
    int b = gq >> 13;
    // lex top-3 of distinct (d, idx) pairs is order-independent
    float B0 = 3.4e38f, B1 = 3.4e38f, B2 = 3.4e38f;
    int   I0 = 0x7fffffff, I1 = 0x7fffffff, I2 = 0x7fffffff;
    #pragma unroll
    for (int t = 0; t < NSPLIT * 3; ++t) {
        float d = g_d2[t][gq];      // coalesced across threads
        int   j = g_i2[t][gq];
        if (kvless(d, j, B2, I2)) {
            if (kvless(d, j, B1, I1)) {
                B2 = B1; I2 = I1;
                if (kvless(d, j, B0, I0)) { B1 = B0; I1 = I0; B0 = d; I0 = j; }
                else                      { B1 = d;  I1 = j; }
            } else { B2 = d; I2 = j; }
        }
    }

    const float* cb = c1 + (size_t)b * N1C * 3;
    const float* ca = cb + (size_t)I0 * 3;   // rank-0 neighbor
    const float* cc = cb + (size_t)I1 * 3;   // rank-1
    const float* cd = cb + (size_t)I2 * 3;   // rank-2
    float* o = out + (size_t)gq * 3;
    #pragma unroll
    for (int c = 0; c < 3; c++) {
        // jnp.mean over K: rn(rn(rn(c0+c1)+c2) / 3)
        float ssum = __fadd_rn(__fadd_rn(ca[c], cc[c]), cd[c]);
        o[c] = __fdiv_rn(ssum, 3.0f);
    }
}

extern "C" void kernel_launch(void* const* d_in, const int* in_sizes, int n_in,
                              void* d_out, int out_size) {
    const float* p1 = (const float*)d_in[0];   // points1 [B, N1, 3]
    const float* p2 = (const float*)d_in[1];   // points2 [B, N2, 3]
    const float* c1 = (const float*)d_in[2];   // colors1 [B, N1, 3]
    float* out = (float*)d_out;                // [B, N2, 3] f32

    knn_pretau<<<NQ / 32, 256>>>(p1, p2);
    dim3 grid(N2C / QPB, NSPLIT, BC);
    knn_main<<<grid, 256>>>(p1, p2);
    knn_merge<<<(NQ + 255) / 256, 256>>>(c1, out);
}